// round 1
// baseline (speedup 1.0000x reference)
#include <cuda_runtime.h>

// EMA final-state: y = sum_{k=0}^{K-1} 0.5^{k+1} * x[b, T-1-k, f]
// Tail beyond K=64 has weight 2^-64 -> negligible vs 1e-3 tolerance.

static constexpr int B = 64;
static constexpr int T = 2048;
static constexpr int F = 512;
static constexpr int K = 64;          // truncation depth (weight 2^-64 tail)
static constexpr int FV = F / 4;      // float4 lanes per row

__global__ void ema_tail_kernel(const float4* __restrict__ x, float4* __restrict__ out) {
    int idx = blockIdx.x * blockDim.x + threadIdx.x;   // 0 .. B*FV-1
    if (idx >= B * FV) return;

    int b  = idx / FV;
    int fv = idx - b * FV;

    // pointer to x[b, T-1, fv] in float4 units
    const float4* p = x + ((size_t)b * T + (T - 1)) * FV + fv;

    float4 acc = make_float4(0.f, 0.f, 0.f, 0.f);
    float w = 0.5f;

    #pragma unroll
    for (int k = 0; k < K; ++k) {
        float4 v = p[-(ptrdiff_t)k * FV];
        acc.x += w * v.x;
        acc.y += w * v.y;
        acc.z += w * v.z;
        acc.w += w * v.w;
        w *= 0.5f;
    }

    out[idx] = acc;   // output [B, 1, F] row-major == [B*FV] float4s
}

extern "C" void kernel_launch(void* const* d_in, const int* in_sizes, int n_in,
                              void* d_out, int out_size) {
    const float4* x = (const float4*)d_in[0];
    float4* out = (float4*)d_out;

    const int total = B * FV;          // 8192 threads
    const int threads = 128;
    const int blocks = (total + threads - 1) / threads;   // 64 blocks
    ema_tail_kernel<<<blocks, threads>>>(x, out);
}

// round 5
// speedup vs baseline: 1.5238x; 1.5238x over previous
#include <cuda_runtime.h>

// EMA final-state: y[b,f] = sum_{k=0}^{K-1} 0.5^{k+1} * x[b, T-1-k, f]
// Tail beyond K=24 has relative weight 2^-24 ~ 6e-8, same order as the fp32
// rounding noise already observed (rel_err 1.3e-7 at K=64), 4 orders below
// the 1e-3 rel-err threshold.
//
// One scalar output element per thread -> 32768 threads for latency hiding;
// warp lanes cover consecutive f, so every k-step load is one coalesced
// 128B line per warp. All K loads are independent -> high MLP.

static constexpr int B = 64;
static constexpr int T = 2048;
static constexpr int F = 512;
static constexpr int K = 24;

__global__ void ema_tail_kernel(const float* __restrict__ x, float* __restrict__ out) {
    int idx = blockIdx.x * blockDim.x + threadIdx.x;   // 0 .. B*F-1
    int b = idx >> 9;          // / 512
    int f = idx & (F - 1);     // % 512

    // base index of x[b, T-1, f]
    size_t base = ((size_t)b * T + (T - 1)) * F + f;

    float acc = 0.f;
    float w = 0.5f;

    #pragma unroll
    for (int k = 0; k < K; ++k) {
        acc = fmaf(w, x[base - (size_t)k * F], acc);
        w *= 0.5f;
    }

    out[idx] = acc;   // [B, 1, F] row-major == [B*F] floats
}

extern "C" void kernel_launch(void* const* d_in, const int* in_sizes, int n_in,
                              void* d_out, int out_size) {
    const float* x = (const float*)d_in[0];
    float* out = (float*)d_out;

    const int total = B * F;            // 32768 threads
    const int threads = 256;
    const int blocks = total / threads; // 128 blocks
    ema_tail_kernel<<<blocks, threads>>>(x, out);
}